// round 11
// baseline (speedup 1.0000x reference)
#include <cuda_runtime.h>
#include <math.h>
#include <cstdint>

// Problem constants
#define BB    128
#define TT    2048
#define DIN   32
#define HH    256
#define G4    1024          // 4*H
#define KK    288           // H + DIN (input projection folded into recurrence)
#define NBLK  128           // persistent recurrence blocks (1/SM, co-resident)
#define MPB   8             // batch rows per block   (16 groups)
#define NPB   32            // h-cols per block       (8 slices)
#define JPB   128           // gate cols per block = 4*NPB
#define HS    10            // h_s row stride (floats): 8B-aligned pairs
#define KPW   36            // k per warp (8 warps * 36 = 288)
#define CLU   8             // cluster size = blocks per batch group

// SMEM layout (floats): buf0[KK*HS], buf1[KK*HS], red_s[64*JPB], mbar(8B)
#define BUF_F   (KK*HS)                 // 2880
#define BUF_B   (BUF_F*4)               // 11520 bytes
#define RED_OFF (2*BUF_F)               // float offset of red_s
#define MBAR_B  ((RED_OFF + 64*JPB)*4)  // byte offset of mbarrier
#define SMEM_BYTES (MBAR_B + 16)

// -------- static device scratch (no allocation allowed) --------
__device__ float g_Wcomb[G4 * DIN];     // W_ih @ W_in   [1024][32]
__device__ float g_bias[G4];            // b_ih + b_hh + W_ih @ b_in
__device__ float g_h[BB][HH];           // final hidden state h(T) only
__device__ float g_emaA[BB * 32 * HH];
__device__ float g_emaP[BB * 32 * HH];
__device__ float g_ema_last[BB * HH];

// ---------------- asm / math helpers -----------------------------------------
__device__ __forceinline__ uint32_t smem_u32(const void* p) {
    uint32_t a;
    asm("{ .reg .u64 t; cvta.to.shared.u64 t, %1; cvt.u32.u64 %0, t; }"
        : "=r"(a) : "l"(p));
    return a;
}
__device__ __forceinline__ float fsig(float x) {          // fast sigmoid
    return __fdividef(1.0f, 1.0f + __expf(-x));
}
__device__ __forceinline__ float ftanh(float x) {         // fast tanh
    return 1.0f - __fdividef(2.0f, __expf(2.0f * x) + 1.0f);
}
__device__ __forceinline__ unsigned long long dup2(float a) {
    unsigned long long r;
    asm("mov.b64 %0, {%1, %1};" : "=l"(r) : "f"(a));
    return r;
}
__device__ __forceinline__ void ffma2(unsigned long long& d,
                                      unsigned long long a, unsigned long long b) {
    asm("fma.rn.f32x2 %0, %1, %2, %0;" : "+l"(d) : "l"(a), "l"(b));
}
__device__ __forceinline__ void unpk(unsigned long long v, float& lo, float& hi) {
    asm("mov.b64 {%0, %1}, %2;" : "=f"(lo), "=f"(hi) : "l"(v));
}
__device__ __forceinline__ uint32_t mapa_u32(uint32_t local, int rank) {
    uint32_t r;
    asm("mapa.shared::cluster.u32 %0, %1, %2;" : "=r"(r) : "r"(local), "r"(rank));
    return r;
}
__device__ __forceinline__ void st_cluster_b32(uint32_t addr, uint32_t v) {
    asm volatile("st.shared::cluster.b32 [%0], %1;" :: "r"(addr), "r"(v) : "memory");
}
__device__ __forceinline__ void mbar_wait_parity(uint32_t mbar, uint32_t parity) {
    uint32_t done = 0;
    do {
        asm volatile(
            "{\n\t.reg .pred p;\n\t"
            "mbarrier.try_wait.parity.acquire.cluster.shared::cta.b64 p, [%1], %2;\n\t"
            "selp.b32 %0, 1, 0, p;\n\t}"
            : "=r"(done) : "r"(mbar), "r"(parity) : "memory");
    } while (!done);
}

// ---------------- prep: W_comb, fused bias ------------------------------------
__global__ void __launch_bounds__(256)
prep_kernel(const float* __restrict__ W_in, const float* __restrict__ b_in,
            const float* __restrict__ W_ih, const float* __restrict__ b_ih,
            const float* __restrict__ b_hh)
{
    int idx = blockIdx.x * 256 + threadIdx.x;
    if (idx < G4 * DIN) {
        int r = idx >> 5;          // gate row 0..1023
        int c = idx & 31;          // input col 0..31
        float s = 0.0f;
        for (int k = 0; k < HH; k++)
            s = fmaf(W_ih[r * HH + k], W_in[k * DIN + c], s);
        g_Wcomb[idx] = s;
    } else if (idx < G4 * DIN + G4) {
        int r = idx - G4 * DIN;
        float s = b_ih[r] + b_hh[r];
        for (int k = 0; k < HH; k++)
            s = fmaf(W_ih[r * HH + k], b_in[k], s);
        g_bias[r] = s;
    }
}

// ---------------- EMA: 64-step chunk -> (A, P) with out = A + P*prev ---------
__global__ void __launch_bounds__(256)
ema_scan_kernel(const float* __restrict__ x,
                const float* __restrict__ W_proj, const float* __restrict__ b_proj,
                const float* __restrict__ W_gate, const float* __restrict__ b_gate)
{
    const int b  = blockIdx.x >> 5;
    const int ch = blockIdx.x & 31;
    const int h  = threadIdx.x;

    __shared__ __align__(16) float x_s[64][DIN];
    for (int i = h; i < 64 * DIN; i += 256) {
        int tt = i >> 5, kk = i & 31;
        x_s[tt][kk] = x[((size_t)b * TT + ch * 64 + tt) * DIN + kk];
    }
    float wz[DIN], wg[DIN];
#pragma unroll
    for (int k = 0; k < DIN; k++) {
        wz[k] = W_proj[h * DIN + k];
        wg[k] = W_gate[h * DIN + k];
    }
    const float bz = b_proj[h], bgv = b_gate[h];
    __syncthreads();

    float A = 0.0f, P = 1.0f;
    for (int tt = 0; tt < 64; tt++) {
        float z = bz, gp = bgv;
#pragma unroll
        for (int q = 0; q < 8; q++) {
            float4 xq = *(const float4*)&x_s[tt][q * 4];
            z  = fmaf(wz[q*4+0], xq.x, z);  z  = fmaf(wz[q*4+1], xq.y, z);
            z  = fmaf(wz[q*4+2], xq.z, z);  z  = fmaf(wz[q*4+3], xq.w, z);
            gp = fmaf(wg[q*4+0], xq.x, gp); gp = fmaf(wg[q*4+1], xq.y, gp);
            gp = fmaf(wg[q*4+2], xq.z, gp); gp = fmaf(wg[q*4+3], xq.w, gp);
        }
        float g  = fsig(gp);
        float om = 1.0f - g;
        A = fmaf(om, A, g * z);
        P *= om;
    }
    g_emaA[((size_t)b * 32 + ch) * HH + h] = A;
    g_emaP[((size_t)b * 32 + ch) * HH + h] = P;
}

__global__ void __launch_bounds__(256) ema_combine_kernel()
{
    const int b = blockIdx.x;
    const int h = threadIdx.x;
    float prev = 0.0f;
#pragma unroll 8
    for (int c = 0; c < 32; c++) {
        float A = g_emaA[((size_t)b * 32 + c) * HH + h];
        float P = g_emaP[((size_t)b * 32 + c) * HH + h];
        prev = fmaf(P, prev, A);
    }
    g_ema_last[b * HH + h] = prev;
}

// ---------------- persistent LSTM recurrence (cluster DSMEM exchange) --------
// 128 blocks = 16 clusters of 8. Cluster = batch group; rank = h-slice.
// Gate threads PUSH h(t+1) into all 8 CTAs' parity buffer via st.shared::cluster,
// then 8 elected threads arrive on each CTA's mbarrier (count 8/phase).
// Matvec/red_s/gate identical to the verified register-weight kernel.
__global__ void __launch_bounds__(256, 1) __cluster_dims__(CLU, 1, 1)
recur_kernel(const float* __restrict__ x, const float* __restrict__ W_hh)
{
    extern __shared__ float sm[];
    float* red_s = sm + RED_OFF;               // [64][128]
    const uint32_t sbase = smem_u32(sm);
    const uint32_t mbar  = sbase + MBAR_B;

    const int tid = threadIdx.x;
    const int bg  = blockIdx.x >> 3;
    const int m0  = bg * MPB;
    const int n0  = (blockIdx.x & 7) * NPB;

    const int wid  = tid >> 5;
    const int lane = tid & 31;
    const int kbase = wid * KPW;    // 8 warps * 36 = 288 = K
    const int mg = tid >> 5;        // gate/staging batch row
    const int hc = tid & 31;        // gate/staging h-col / x-col

    // one-time: weight slice into registers (identical to round-9 layout)
    float4 wreg[KPW];
#pragma unroll
    for (int kk = 0; kk < KPW; kk++) {
        const int k = kbase + kk;
        float4 w;
        if (k < HH) {
            w.x = W_hh[(0 * 256 + n0 + lane) * HH + k];
            w.y = W_hh[(1 * 256 + n0 + lane) * HH + k];
            w.z = W_hh[(2 * 256 + n0 + lane) * HH + k];
            w.w = W_hh[(3 * 256 + n0 + lane) * HH + k];
        } else {
            const int kc = k - HH;
            w.x = g_Wcomb[(0 * 256 + n0 + lane) * DIN + kc];
            w.y = g_Wcomb[(1 * 256 + n0 + lane) * DIN + kc];
            w.z = g_Wcomb[(2 * 256 + n0 + lane) * DIN + kc];
            w.w = g_Wcomb[(3 * 256 + n0 + lane) * DIN + kc];
        }
        wreg[kk] = w;
    }
    const float4 bv = make_float4(g_bias[0 * 256 + n0 + hc],
                                  g_bias[1 * 256 + n0 + hc],
                                  g_bias[2 * 256 + n0 + hc],
                                  g_bias[3 * 256 + n0 + hc]);

    // mapa bases for the 8 cluster ranks (constant-indexed -> stays in regs)
    uint32_t rbase[CLU];
#pragma unroll
    for (int r = 0; r < CLU; r++) rbase[r] = mapa_u32(sbase, r);
    const uint32_t myoff = (uint32_t)(((n0 + hc) * HS + mg) * 4);  // h push offset
    uint32_t arr_addr = 0;
    if (tid < CLU) arr_addr = mapa_u32(mbar, tid);                  // my arrive target

    // init: mbarrier (count = 8 arrivals per phase) + zero buf0 (h(0) = 0)
    if (tid == 0)
        asm volatile("mbarrier.init.shared.b64 [%0], %1;"
                     :: "r"(mbar), "r"(CLU) : "memory");
    for (int i = tid; i < BUF_F; i += 256) sm[i] = 0.0f;
    __syncthreads();
    asm volatile("barrier.cluster.arrive.aligned;" ::: "memory");
    asm volatile("barrier.cluster.wait.aligned;"   ::: "memory");

    float c_val = 0.0f;

    for (int t = 0; t < TT; t++) {
        float* hb = sm + (t & 1) * BUF_F;
        // prefetch x_t (overlaps the mbar wait)
        const float xv = __ldg(&x[((size_t)(m0 + mg) * TT + t) * DIN + hc]);

        if (t > 0) mbar_wait_parity(mbar, (uint32_t)((t - 1) & 1));
        hb[(HH + hc) * HS + mg] = xv;          // x region: local-only, no hazard
        __syncthreads();

        // K-split matvec, f32x2 over batch-row pairs, W in registers
        {
            unsigned long long acc2[4][4];     // [m-pair][gate]
#pragma unroll
            for (int mp = 0; mp < 4; mp++)
#pragma unroll
                for (int c = 0; c < 4; c++) acc2[mp][c] = 0ull;

#pragma unroll
            for (int kk = 0; kk < KPW; kk++) {
                const int k = kbase + kk;
                const unsigned long long hp[4] = {
                    *(const unsigned long long*)&hb[k * HS + 0],
                    *(const unsigned long long*)&hb[k * HS + 2],
                    *(const unsigned long long*)&hb[k * HS + 4],
                    *(const unsigned long long*)&hb[k * HS + 6] };
                const float4 wv = wreg[kk];
                const unsigned long long wd[4] =
                    { dup2(wv.x), dup2(wv.y), dup2(wv.z), dup2(wv.w) };
#pragma unroll
                for (int mp = 0; mp < 4; mp++) {
                    ffma2(acc2[mp][0], hp[mp], wd[0]);
                    ffma2(acc2[mp][1], hp[mp], wd[1]);
                    ffma2(acc2[mp][2], hp[mp], wd[2]);
                    ffma2(acc2[mp][3], hp[mp], wd[3]);
                }
            }

            float a[MPB][4];
#pragma unroll
            for (int mp = 0; mp < 4; mp++)
#pragma unroll
                for (int c = 0; c < 4; c++)
                    unpk(acc2[mp][c], a[2 * mp][c], a[2 * mp + 1][c]);
#pragma unroll
            for (int m = 0; m < MPB; m++)
                *(float4*)&red_s[(wid * MPB + m) * JPB + lane * 4] =
                    make_float4(a[m][0], a[m][1], a[m][2], a[m][3]);
        }
        __syncthreads();

        // gate phase: reduce 8 k-partials (float4), activations, PUSH h(t+1)
        {
            float4 sv = bv;
#pragma unroll
            for (int tk = 0; tk < 8; tk++) {
                const float4 r4 =
                    *(const float4*)&red_s[(tk * MPB + mg) * JPB + hc * 4];
                sv.x += r4.x; sv.y += r4.y; sv.z += r4.z; sv.w += r4.w;
            }
            const float ig = fsig(sv.x);
            const float fg = fsig(sv.y);
            const float gg = ftanh(sv.z);
            const float og = fsig(sv.w);
            c_val = fmaf(fg, c_val, ig * gg);
            const float hval = og * ftanh(c_val);

            const uint32_t boff = (uint32_t)(((t + 1) & 1) * BUF_B) + myoff;
            const uint32_t hvb  = __float_as_uint(hval);
#pragma unroll
            for (int r = 0; r < CLU; r++)
                st_cluster_b32(rbase[r] + boff, hvb);

            if (t == TT - 1)
                g_h[m0 + mg][n0 + hc] = hval;   // final state for head
        }
        __syncthreads();                        // all pushes issued block-wide

        if (tid < CLU) {                        // one arrive per destination CTA
            asm volatile("fence.acq_rel.cluster;" ::: "memory");
            asm volatile(
                "mbarrier.arrive.release.cluster.shared::cluster.b64 _, [%0];"
                :: "r"(arr_addr) : "memory");
        }
    }

    // no CTA may exit while peers' DSMEM stores/arrives may still target it
    asm volatile("barrier.cluster.arrive.aligned;" ::: "memory");
    asm volatile("barrier.cluster.wait.aligned;"   ::: "memory");
}

// ---------------- head: concat -> LayerNorm -> GELU(erf) MLP -> out ---------
__global__ void __launch_bounds__(256)
head_kernel(const float* __restrict__ ln_scale, const float* __restrict__ ln_bias,
            const float* __restrict__ W_h1, const float* __restrict__ b_h1,
            const float* __restrict__ W_h2, const float* __restrict__ b_h2,
            float* __restrict__ out)
{
    __shared__ __align__(16) float ns[512];
    __shared__ float red[32];
    __shared__ float mu_s, rv_s;

    const int b = blockIdx.x;
    const int tid = threadIdx.x;

    const float v0 = g_h[b][tid];
    const float v1 = g_ema_last[b * HH + tid];

    float s = v0 + v1, sq = v0 * v0 + v1 * v1;
#pragma unroll
    for (int o = 16; o; o >>= 1) {
        s  += __shfl_down_sync(0xffffffffu, s,  o);
        sq += __shfl_down_sync(0xffffffffu, sq, o);
    }
    if ((tid & 31) == 0) { red[tid >> 5] = s; red[8 + (tid >> 5)] = sq; }
    __syncthreads();
    if (tid == 0) {
        float ts = 0.f, tq = 0.f;
        for (int i = 0; i < 8; i++) { ts += red[i]; tq += red[8 + i]; }
        float mu = ts / 512.0f;
        mu_s = mu;
        rv_s = rsqrtf(tq / 512.0f - mu * mu + 1e-5f);
    }
    __syncthreads();
    const float mu = mu_s, ri = rv_s;
    ns[tid]       = fmaf((v0 - mu) * ri, ln_scale[tid],       ln_bias[tid]);
    ns[tid + 256] = fmaf((v1 - mu) * ri, ln_scale[tid + 256], ln_bias[tid + 256]);
    __syncthreads();

    float acc = b_h1[tid];
    const float4* wr = (const float4*)(W_h1 + (size_t)tid * 512);
#pragma unroll 8
    for (int q = 0; q < 128; q++) {
        float4 w = wr[q];
        float4 n = *(const float4*)&ns[q * 4];
        acc = fmaf(w.x, n.x, acc); acc = fmaf(w.y, n.y, acc);
        acc = fmaf(w.z, n.z, acc); acc = fmaf(w.w, n.w, acc);
    }
    float g1 = 0.5f * acc * (1.0f + erff(acc * 0.70710678118654752f));
    float p = g1 * W_h2[tid];
#pragma unroll
    for (int o = 16; o; o >>= 1) p += __shfl_down_sync(0xffffffffu, p, o);
    if ((tid & 31) == 0) red[16 + (tid >> 5)] = p;
    __syncthreads();
    if (tid == 0) {
        float tsum = b_h2[0];
        for (int i = 0; i < 8; i++) tsum += red[16 + i];
        out[b] = tsum;
    }
}

// ---------------- launch ----------------------------------------------------
extern "C" void kernel_launch(void* const* d_in, const int* in_sizes, int n_in,
                              void* d_out, int out_size)
{
    (void)in_sizes; (void)n_in; (void)out_size;
    const float* x        = (const float*)d_in[0];
    const float* W_in     = (const float*)d_in[1];
    const float* b_in     = (const float*)d_in[2];
    const float* W_ih     = (const float*)d_in[3];
    const float* W_hh     = (const float*)d_in[4];
    const float* b_ih     = (const float*)d_in[5];
    const float* b_hh     = (const float*)d_in[6];
    const float* W_proj   = (const float*)d_in[7];
    const float* b_proj   = (const float*)d_in[8];
    const float* W_gate   = (const float*)d_in[9];
    const float* b_gate   = (const float*)d_in[10];
    const float* ln_scale = (const float*)d_in[11];
    const float* ln_bias  = (const float*)d_in[12];
    const float* W_h1     = (const float*)d_in[13];
    const float* b_h1     = (const float*)d_in[14];
    const float* W_h2     = (const float*)d_in[15];
    const float* b_h2     = (const float*)d_in[16];
    float* out = (float*)d_out;

    cudaFuncSetAttribute(recur_kernel,
                         cudaFuncAttributeMaxDynamicSharedMemorySize, SMEM_BYTES);

    prep_kernel<<<132, 256>>>(W_in, b_in, W_ih, b_ih, b_hh);
    recur_kernel<<<NBLK, 256, SMEM_BYTES>>>(x, W_hh);
    ema_scan_kernel<<<BB * 32, 256>>>(x, W_proj, b_proj, W_gate, b_gate);
    ema_combine_kernel<<<BB, 256>>>();
    head_kernel<<<BB, 256>>>(ln_scale, ln_bias, W_h1, b_h1, W_h2, b_h2, out);
}

// round 13
// speedup vs baseline: 2.6265x; 2.6265x over previous
#include <cuda_runtime.h>
#include <cuda_bf16.h>
#include <math.h>
#include <cstdint>

// Problem constants
#define BB    128
#define TT    2048
#define DIN   32
#define HH    256
#define G4    1024          // 4*H
#define KK    288           // H + DIN (input projection folded into recurrence)
#define NBLK  128           // persistent recurrence blocks (1/SM, co-resident)
#define MPB   8             // batch rows per block   (16 groups)
#define NPB   32            // h-cols per block       (8 slices)
#define NGRP  16            // batch groups
#define NKT   18            // k-tiles of 16 (288)
#define NPAIR 144           // 288 k as bf16 pairs
#define JST   132           // exch row stride (floats), conflict-free epilogue

// SMEM (u32 words): hs2a[1152], hs2b[1152], exch(float)[8*JST]
#define HS2A_OFF 0
#define HS2B_OFF 1152
#define EXCH_OFF 2304
#define SMEM_BYTES ((EXCH_OFF + 8*JST) * 4)

// -------- static device scratch (no allocation allowed) --------
__device__ float g_Wcomb[G4 * DIN];     // W_ih @ W_in   [1024][32]
__device__ float g_bias[G4];            // b_ih + b_hh + W_ih @ b_in
__device__ float g_h[2][BB][HH];        // double-buffered hidden state
__device__ float g_emaA[BB * 32 * HH];
__device__ float g_emaP[BB * 32 * HH];
__device__ float g_ema_last[BB * HH];
__device__ unsigned g_cnt[NGRP * 32];   // per-group arrival counters (128B apart)

// ---------------- asm / math helpers -----------------------------------------
__device__ __forceinline__ unsigned ld_acq(const unsigned* p) {
    unsigned v;
    asm volatile("ld.acquire.gpu.global.u32 %0, [%1];" : "=r"(v) : "l"(p));
    return v;
}
__device__ __forceinline__ void red_add_release(unsigned* p, unsigned v) {
    asm volatile("red.release.gpu.global.add.u32 [%0], %1;" :: "l"(p), "r"(v) : "memory");
}
__device__ __forceinline__ float fsig(float x) {
    return __fdividef(1.0f, 1.0f + __expf(-x));
}
__device__ __forceinline__ float ftanh(float x) {
    return 1.0f - __fdividef(2.0f, __expf(2.0f * x) + 1.0f);
}
__device__ __forceinline__ void mma16816(float& d0, float& d1, float& d2, float& d3,
                                         uint32_t a0, uint32_t a1, uint32_t a2, uint32_t a3,
                                         uint32_t b0, uint32_t b1) {
    asm volatile(
        "mma.sync.aligned.m16n8k16.row.col.f32.bf16.bf16.f32 "
        "{%0,%1,%2,%3}, {%4,%5,%6,%7}, {%8,%9}, {%0,%1,%2,%3};"
        : "+f"(d0), "+f"(d1), "+f"(d2), "+f"(d3)
        : "r"(a0), "r"(a1), "r"(a2), "r"(a3), "r"(b0), "r"(b1));
}
__device__ __forceinline__ unsigned short bfb(__nv_bfloat16 b) {
    return *(unsigned short*)&b;
}
// pack Dekker-split bf16 pairs of (v0, v1) -> (hi split1, hi split2)
__device__ __forceinline__ void split_pack(float v0, float v1,
                                           uint32_t& s1, uint32_t& s2) {
    __nv_bfloat16 a1 = __float2bfloat16(v0);
    __nv_bfloat16 a2 = __float2bfloat16(v0 - __bfloat162float(a1));
    __nv_bfloat16 b1 = __float2bfloat16(v1);
    __nv_bfloat16 b2 = __float2bfloat16(v1 - __bfloat162float(b1));
    s1 = (uint32_t)bfb(a1) | ((uint32_t)bfb(b1) << 16);
    s2 = (uint32_t)bfb(a2) | ((uint32_t)bfb(b2) << 16);
}

// ---------------- prep: W_comb, fused bias, zero h(0), zero counters ---------
__global__ void __launch_bounds__(256)
prep_kernel(const float* __restrict__ W_in, const float* __restrict__ b_in,
            const float* __restrict__ W_ih, const float* __restrict__ b_ih,
            const float* __restrict__ b_hh)
{
    int idx = blockIdx.x * 256 + threadIdx.x;
    if (idx < NGRP * 32) g_cnt[idx] = 0u;
    if (idx < G4 * DIN) {
        int r = idx >> 5;
        int c = idx & 31;
        float s = 0.0f;
        for (int k = 0; k < HH; k++)
            s = fmaf(W_ih[r * HH + k], W_in[k * DIN + c], s);
        g_Wcomb[idx] = s;
        ((float*)g_h)[idx] = 0.0f;             // zero buffer 0 = h(0)
    } else if (idx < G4 * DIN + G4) {
        int r = idx - G4 * DIN;
        float s = b_ih[r] + b_hh[r];
        for (int k = 0; k < HH; k++)
            s = fmaf(W_ih[r * HH + k], b_in[k], s);
        g_bias[r] = s;
    }
}

// ---------------- EMA path (unchanged, verified) ------------------------------
__global__ void __launch_bounds__(256)
ema_scan_kernel(const float* __restrict__ x,
                const float* __restrict__ W_proj, const float* __restrict__ b_proj,
                const float* __restrict__ W_gate, const float* __restrict__ b_gate)
{
    const int b  = blockIdx.x >> 5;
    const int ch = blockIdx.x & 31;
    const int h  = threadIdx.x;

    __shared__ __align__(16) float x_s[64][DIN];
    for (int i = h; i < 64 * DIN; i += 256) {
        int tt = i >> 5, kk = i & 31;
        x_s[tt][kk] = x[((size_t)b * TT + ch * 64 + tt) * DIN + kk];
    }
    float wz[DIN], wg[DIN];
#pragma unroll
    for (int k = 0; k < DIN; k++) {
        wz[k] = W_proj[h * DIN + k];
        wg[k] = W_gate[h * DIN + k];
    }
    const float bz = b_proj[h], bgv = b_gate[h];
    __syncthreads();

    float A = 0.0f, P = 1.0f;
    for (int tt = 0; tt < 64; tt++) {
        float z = bz, gp = bgv;
#pragma unroll
        for (int q = 0; q < 8; q++) {
            float4 xq = *(const float4*)&x_s[tt][q * 4];
            z  = fmaf(wz[q*4+0], xq.x, z);  z  = fmaf(wz[q*4+1], xq.y, z);
            z  = fmaf(wz[q*4+2], xq.z, z);  z  = fmaf(wz[q*4+3], xq.w, z);
            gp = fmaf(wg[q*4+0], xq.x, gp); gp = fmaf(wg[q*4+1], xq.y, gp);
            gp = fmaf(wg[q*4+2], xq.z, gp); gp = fmaf(wg[q*4+3], xq.w, gp);
        }
        float g  = fsig(gp);
        float om = 1.0f - g;
        A = fmaf(om, A, g * z);
        P *= om;
    }
    g_emaA[((size_t)b * 32 + ch) * HH + h] = A;
    g_emaP[((size_t)b * 32 + ch) * HH + h] = P;
}

__global__ void __launch_bounds__(256) ema_combine_kernel()
{
    const int b = blockIdx.x;
    const int h = threadIdx.x;
    float prev = 0.0f;
#pragma unroll 8
    for (int c = 0; c < 32; c++) {
        float A = g_emaA[((size_t)b * 32 + c) * HH + h];
        float P = g_emaP[((size_t)b * 32 + c) * HH + h];
        prev = fmaf(P, prev, A);
    }
    g_ema_last[b * HH + h] = prev;
}

// ---------------- persistent LSTM recurrence: HMMA bf16 2-split --------------
// 128 blocks = 16 groups x 8 slices; round-9 L2 exchange + group counters.
// Warp w owns j-tile [16w,16w+16); per step: 18 k-tiles x 3 split-products of
// mma.m16n8k16 (A=W row-major frags in regs, B=h col-major frags from SMEM).
// j -> gate row r = (j&3)*256 + n0 + (j>>2)  (so gate phase reads float4 quads).
__global__ void __launch_bounds__(256, 1)
recur_kernel(const float* __restrict__ x, const float* __restrict__ W_hh)
{
    extern __shared__ uint32_t smu[];
    uint32_t* hs2a = smu + HS2A_OFF;           // [144 kp][8 m] split-1 pairs
    uint32_t* hs2b = smu + HS2B_OFF;           // [144 kp][8 m] split-2 pairs
    float*    exch = (float*)(smu + EXCH_OFF); // [8 m][JST]

    const int tid  = threadIdx.x;
    const int bg   = blockIdx.x >> 3;
    const int m0   = bg * MPB;
    const int n0   = (blockIdx.x & 7) * NPB;
    const int wid  = tid >> 5;
    const int lane = tid & 31;
    const int g    = lane >> 2;     // fragment group id (row-within-tile / n col)
    const int tig  = lane & 3;      // thread-in-group
    const int mg   = tid >> 5;      // gate-phase batch row
    const int hc   = tid & 31;      // gate-phase h-col

    // this thread's two j rows and their gate rows / biases
    const int j0 = wid * 16 + g;
    const int j1 = j0 + 8;
    const int r0 = ((j0 & 3) << 8) + n0 + (j0 >> 2);
    const int r1 = ((j1 & 3) << 8) + n0 + (j1 >> 2);
    const float br0 = g_bias[r0];
    const float br1 = g_bias[r1];

    // ---- one-time: A fragments (W 2-split) into registers ----
    // slot0:(r0, k+2tig) slot1:(r1, k+2tig) slot2:(r0, k+2tig+8) slot3:(r1, +8)
    uint32_t aw1[NKT][4], aw2[NKT][4];
#pragma unroll
    for (int kt = 0; kt < NKT; kt++) {
        const int kb = kt * 16 + 2 * tig;
#pragma unroll
        for (int sl = 0; sl < 4; sl++) {
            const int r = (sl & 1) ? r1 : r0;
            const int k = kb + ((sl >> 1) ? 8 : 0);
            float v0, v1;
            v0 = (k < HH)     ? W_hh[r * HH + k]     : g_Wcomb[r * DIN + (k - HH)];
            v1 = (k + 1 < HH) ? W_hh[r * HH + k + 1] : g_Wcomb[r * DIN + (k + 1 - HH)];
            split_pack(v0, v1, aw1[kt][sl], aw2[kt][sl]);
        }
    }

    float c_val = 0.0f;
    unsigned* cnt = &g_cnt[bg * 32];

    for (int t = 0; t < TT; t++) {
        const int p = t & 1;

        // ---- stage h(t)+x_t as split bf16 pairs: hs2[kp][m] ----
#pragma unroll
        for (int it = 0; it < 5; it++) {
            const int i = tid + it * 256;
            if (i < NPAIR * MPB) {
                const int m  = i / NPAIR;
                const int kp = i - m * NPAIR;
                float2 v;
                if (kp < 128)
                    v = __ldcg((const float2*)&g_h[p][m0 + m][2 * kp]);
                else
                    v = *(const float2*)&x[((size_t)(m0 + m) * TT + t) * DIN
                                           + 2 * (kp - 128)];
                uint32_t s1, s2;
                split_pack(v.x, v.y, s1, s2);
                hs2a[kp * 8 + m] = s1;
                hs2b[kp * 8 + m] = s2;
            }
        }
        __syncthreads();

        // ---- HMMA: D(j-tile, 8m) = W1*h1 + W1*h2 + W2*h1 (+bias in C) ----
        float d0 = br0, d1 = br0, d2 = br1, d3 = br1;
#pragma unroll
        for (int kt = 0; kt < NKT; kt++) {
            const uint32_t bA0 = hs2a[(kt * 8 + tig) * 8 + g];
            const uint32_t bA1 = hs2a[(kt * 8 + tig + 4) * 8 + g];
            const uint32_t bB0 = hs2b[(kt * 8 + tig) * 8 + g];
            const uint32_t bB1 = hs2b[(kt * 8 + tig + 4) * 8 + g];
            mma16816(d0, d1, d2, d3,
                     aw1[kt][0], aw1[kt][1], aw1[kt][2], aw1[kt][3], bA0, bA1);
            mma16816(d0, d1, d2, d3,
                     aw1[kt][0], aw1[kt][1], aw1[kt][2], aw1[kt][3], bB0, bB1);
            mma16816(d0, d1, d2, d3,
                     aw2[kt][0], aw2[kt][1], aw2[kt][2], aw2[kt][3], bA0, bA1);
        }

        // ---- epilogue: D frags -> exch[m][j] (JST=132 conflict-free) ----
        exch[(2 * tig)     * JST + j0] = d0;
        exch[(2 * tig + 1) * JST + j0] = d1;
        exch[(2 * tig)     * JST + j1] = d2;
        exch[(2 * tig + 1) * JST + j1] = d3;
        __syncthreads();

        // ---- gate phase: (mg, hc) reads quad (i,f,g,o), publish h(t+1) ----
        {
            const float4 q4 = *(const float4*)&exch[mg * JST + hc * 4];
            const float ig = fsig(q4.x);
            const float fg = fsig(q4.y);
            const float gg = ftanh(q4.z);
            const float og = fsig(q4.w);
            c_val = fmaf(fg, c_val, ig * gg);
            g_h[p ^ 1][m0 + mg][n0 + hc] = og * ftanh(c_val);
        }

        // ---- scoped group barrier (round-9 proven) ----
        __syncthreads();
        if (tid == 0) {
            red_add_release(cnt, 1u);
            const unsigned tgt = 8u * (unsigned)(t + 1);
            while (ld_acq(cnt) < tgt) { }
        }
        __syncthreads();
    }
    // h_last = h(2048) lives in g_h[0]
}

// ---------------- head: concat -> LayerNorm -> GELU(erf) MLP -> out ---------
__global__ void __launch_bounds__(256)
head_kernel(const float* __restrict__ ln_scale, const float* __restrict__ ln_bias,
            const float* __restrict__ W_h1, const float* __restrict__ b_h1,
            const float* __restrict__ W_h2, const float* __restrict__ b_h2,
            float* __restrict__ out)
{
    __shared__ __align__(16) float ns[512];
    __shared__ float red[32];
    __shared__ float mu_s, rv_s;

    const int b = blockIdx.x;
    const int tid = threadIdx.x;

    const float v0 = g_h[0][b][tid];
    const float v1 = g_ema_last[b * HH + tid];

    float s = v0 + v1, sq = v0 * v0 + v1 * v1;
#pragma unroll
    for (int o = 16; o; o >>= 1) {
        s  += __shfl_down_sync(0xffffffffu, s,  o);
        sq += __shfl_down_sync(0xffffffffu, sq, o);
    }
    if ((tid & 31) == 0) { red[tid >> 5] = s; red[8 + (tid >> 5)] = sq; }
    __syncthreads();
    if (tid == 0) {
        float ts = 0.f, tq = 0.f;
        for (int i = 0; i < 8; i++) { ts += red[i]; tq += red[8 + i]; }
        float mu = ts / 512.0f;
        mu_s = mu;
        rv_s = rsqrtf(tq / 512.0f - mu * mu + 1e-5f);
    }
    __syncthreads();
    const float mu = mu_s, ri = rv_s;
    ns[tid]       = fmaf((v0 - mu) * ri, ln_scale[tid],       ln_bias[tid]);
    ns[tid + 256] = fmaf((v1 - mu) * ri, ln_scale[tid + 256], ln_bias[tid + 256]);
    __syncthreads();

    float acc = b_h1[tid];
    const float4* wr = (const float4*)(W_h1 + (size_t)tid * 512);
#pragma unroll 8
    for (int q = 0; q < 128; q++) {
        float4 w = wr[q];
        float4 n = *(const float4*)&ns[q * 4];
        acc = fmaf(w.x, n.x, acc); acc = fmaf(w.y, n.y, acc);
        acc = fmaf(w.z, n.z, acc); acc = fmaf(w.w, n.w, acc);
    }
    float g1 = 0.5f * acc * (1.0f + erff(acc * 0.70710678118654752f));
    float p = g1 * W_h2[tid];
#pragma unroll
    for (int o = 16; o; o >>= 1) p += __shfl_down_sync(0xffffffffu, p, o);
    if ((tid & 31) == 0) red[16 + (tid >> 5)] = p;
    __syncthreads();
    if (tid == 0) {
        float tsum = b_h2[0];
        for (int i = 0; i < 8; i++) tsum += red[16 + i];
        out[b] = tsum;
    }
}

// ---------------- launch ----------------------------------------------------
extern "C" void kernel_launch(void* const* d_in, const int* in_sizes, int n_in,
                              void* d_out, int out_size)
{
    (void)in_sizes; (void)n_in; (void)out_size;
    const float* x        = (const float*)d_in[0];
    const float* W_in     = (const float*)d_in[1];
    const float* b_in     = (const float*)d_in[2];
    const float* W_ih     = (const float*)d_in[3];
    const float* W_hh     = (const float*)d_in[4];
    const float* b_ih     = (const float*)d_in[5];
    const float* b_hh     = (const float*)d_in[6];
    const float* W_proj   = (const float*)d_in[7];
    const float* b_proj   = (const float*)d_in[8];
    const float* W_gate   = (const float*)d_in[9];
    const float* b_gate   = (const float*)d_in[10];
    const float* ln_scale = (const float*)d_in[11];
    const float* ln_bias  = (const float*)d_in[12];
    const float* W_h1     = (const float*)d_in[13];
    const float* b_h1     = (const float*)d_in[14];
    const float* W_h2     = (const float*)d_in[15];
    const float* b_h2     = (const float*)d_in[16];
    float* out = (float*)d_out;

    cudaFuncSetAttribute(recur_kernel,
                         cudaFuncAttributeMaxDynamicSharedMemorySize, SMEM_BYTES);

    prep_kernel<<<132, 256>>>(W_in, b_in, W_ih, b_ih, b_hh);
    recur_kernel<<<NBLK, 256, SMEM_BYTES>>>(x, W_hh);
    ema_scan_kernel<<<BB * 32, 256>>>(x, W_proj, b_proj, W_gate, b_gate);
    ema_combine_kernel<<<BB, 256>>>();
    head_kernel<<<BB, 256>>>(ln_scale, ln_bias, W_h1, b_h1, W_h2, b_h2, out);
}

// round 14
// speedup vs baseline: 2.8847x; 1.0983x over previous
#include <cuda_runtime.h>
#include <cuda_bf16.h>
#include <math.h>
#include <cstdint>

// Problem constants
#define BB    128
#define TT    2048
#define DIN   32
#define HH    256
#define G4    1024          // 4*H
#define KK    288           // H + DIN (input projection folded into recurrence)
#define NBLK  128           // persistent recurrence blocks (1/SM, co-resident)
#define MPB   8             // batch rows per block   (16 groups)
#define NPB   32            // h-cols per block       (8 slices)
#define NGRP  16            // batch groups
#define NKT   18            // k-tiles of 16 (288)
#define NPAIR 144           // 288 k as bf16 pairs
#define JST   132           // exch row stride (floats), conflict-free epilogue

// SMEM (u32 words): hs2a[1152], hs2b[1152], exch(float)[8*JST]
#define HS2A_OFF 0
#define HS2B_OFF 1152
#define EXCH_OFF 2304
#define SMEM_BYTES ((EXCH_OFF + 8*JST) * 4)

// -------- static device scratch (no allocation allowed) --------
__device__ float g_Wcomb[G4 * DIN];     // W_ih @ W_in   [1024][32]
__device__ float g_bias[G4];            // b_ih + b_hh + W_ih @ b_in
__device__ float g_h[2][BB][HH];        // double-buffered hidden state
__device__ float g_emaA[BB * 32 * HH];
__device__ float g_emaP[BB * 32 * HH];
__device__ float g_ema_last[BB * HH];
__device__ unsigned g_cnt[NGRP * 32];   // per-group arrival counters (128B apart)

// ---------------- asm / math helpers -----------------------------------------
__device__ __forceinline__ unsigned ld_acq(const unsigned* p) {
    unsigned v;
    asm volatile("ld.acquire.gpu.global.u32 %0, [%1];" : "=r"(v) : "l"(p));
    return v;
}
__device__ __forceinline__ void red_add_release(unsigned* p, unsigned v) {
    asm volatile("red.release.gpu.global.add.u32 [%0], %1;" :: "l"(p), "r"(v) : "memory");
}
__device__ __forceinline__ float fsig(float x) {
    return __fdividef(1.0f, 1.0f + __expf(-x));
}
__device__ __forceinline__ float ftanh(float x) {
    return 1.0f - __fdividef(2.0f, __expf(2.0f * x) + 1.0f);
}
__device__ __forceinline__ void mma16816(float& d0, float& d1, float& d2, float& d3,
                                         uint32_t a0, uint32_t a1, uint32_t a2, uint32_t a3,
                                         uint32_t b0, uint32_t b1) {
    asm volatile(
        "mma.sync.aligned.m16n8k16.row.col.f32.bf16.bf16.f32 "
        "{%0,%1,%2,%3}, {%4,%5,%6,%7}, {%8,%9}, {%0,%1,%2,%3};"
        : "+f"(d0), "+f"(d1), "+f"(d2), "+f"(d3)
        : "r"(a0), "r"(a1), "r"(a2), "r"(a3), "r"(b0), "r"(b1));
}
__device__ __forceinline__ unsigned short bfb(__nv_bfloat16 b) {
    return *(unsigned short*)&b;
}
// pack Dekker-split bf16 pairs of (v0, v1) -> (hi split1, hi split2)
__device__ __forceinline__ void split_pack(float v0, float v1,
                                           uint32_t& s1, uint32_t& s2) {
    __nv_bfloat16 a1 = __float2bfloat16(v0);
    __nv_bfloat16 a2 = __float2bfloat16(v0 - __bfloat162float(a1));
    __nv_bfloat16 b1 = __float2bfloat16(v1);
    __nv_bfloat16 b2 = __float2bfloat16(v1 - __bfloat162float(b1));
    s1 = (uint32_t)bfb(a1) | ((uint32_t)bfb(b1) << 16);
    s2 = (uint32_t)bfb(a2) | ((uint32_t)bfb(b2) << 16);
}

// ---------------- prep: W_comb, fused bias, zero h(0), zero counters ---------
__global__ void __launch_bounds__(256)
prep_kernel(const float* __restrict__ W_in, const float* __restrict__ b_in,
            const float* __restrict__ W_ih, const float* __restrict__ b_ih,
            const float* __restrict__ b_hh)
{
    int idx = blockIdx.x * 256 + threadIdx.x;
    if (idx < NGRP * 32) g_cnt[idx] = 0u;
    if (idx < G4 * DIN) {
        int r = idx >> 5;
        int c = idx & 31;
        float s = 0.0f;
        for (int k = 0; k < HH; k++)
            s = fmaf(W_ih[r * HH + k], W_in[k * DIN + c], s);
        g_Wcomb[idx] = s;
        ((float*)g_h)[idx] = 0.0f;             // zero buffer 0 = h(0)
    } else if (idx < G4 * DIN + G4) {
        int r = idx - G4 * DIN;
        float s = b_ih[r] + b_hh[r];
        for (int k = 0; k < HH; k++)
            s = fmaf(W_ih[r * HH + k], b_in[k], s);
        g_bias[r] = s;
    }
}

// ---------------- EMA path (unchanged, verified) ------------------------------
__global__ void __launch_bounds__(256)
ema_scan_kernel(const float* __restrict__ x,
                const float* __restrict__ W_proj, const float* __restrict__ b_proj,
                const float* __restrict__ W_gate, const float* __restrict__ b_gate)
{
    const int b  = blockIdx.x >> 5;
    const int ch = blockIdx.x & 31;
    const int h  = threadIdx.x;

    __shared__ __align__(16) float x_s[64][DIN];
    for (int i = h; i < 64 * DIN; i += 256) {
        int tt = i >> 5, kk = i & 31;
        x_s[tt][kk] = x[((size_t)b * TT + ch * 64 + tt) * DIN + kk];
    }
    float wz[DIN], wg[DIN];
#pragma unroll
    for (int k = 0; k < DIN; k++) {
        wz[k] = W_proj[h * DIN + k];
        wg[k] = W_gate[h * DIN + k];
    }
    const float bz = b_proj[h], bgv = b_gate[h];
    __syncthreads();

    float A = 0.0f, P = 1.0f;
    for (int tt = 0; tt < 64; tt++) {
        float z = bz, gp = bgv;
#pragma unroll
        for (int q = 0; q < 8; q++) {
            float4 xq = *(const float4*)&x_s[tt][q * 4];
            z  = fmaf(wz[q*4+0], xq.x, z);  z  = fmaf(wz[q*4+1], xq.y, z);
            z  = fmaf(wz[q*4+2], xq.z, z);  z  = fmaf(wz[q*4+3], xq.w, z);
            gp = fmaf(wg[q*4+0], xq.x, gp); gp = fmaf(wg[q*4+1], xq.y, gp);
            gp = fmaf(wg[q*4+2], xq.z, gp); gp = fmaf(wg[q*4+3], xq.w, gp);
        }
        float g  = fsig(gp);
        float om = 1.0f - g;
        A = fmaf(om, A, g * z);
        P *= om;
    }
    g_emaA[((size_t)b * 32 + ch) * HH + h] = A;
    g_emaP[((size_t)b * 32 + ch) * HH + h] = P;
}

__global__ void __launch_bounds__(256) ema_combine_kernel()
{
    const int b = blockIdx.x;
    const int h = threadIdx.x;
    float prev = 0.0f;
#pragma unroll 8
    for (int c = 0; c < 32; c++) {
        float A = g_emaA[((size_t)b * 32 + c) * HH + h];
        float P = g_emaP[((size_t)b * 32 + c) * HH + h];
        prev = fmaf(P, prev, A);
    }
    g_ema_last[b * HH + h] = prev;
}

// ---------------- persistent LSTM recurrence: HMMA bf16 2-split --------------
// 128 blocks = 16 groups x 8 slices; round-9 L2 exchange + group counters.
// Warp w owns j-tile [16w,16w+16); per step: 18 k-tiles x 3 split-products of
// mma.m16n8k16 in THREE INDEPENDENT accumulator chains (depth 18 each),
// summed after the k-loop. Staging batches its 5 L2 loads (MLP=5) first.
__global__ void __launch_bounds__(256, 1)
recur_kernel(const float* __restrict__ x, const float* __restrict__ W_hh)
{
    extern __shared__ uint32_t smu[];
    uint32_t* hs2a = smu + HS2A_OFF;           // [144 kp][8 m] split-1 pairs
    uint32_t* hs2b = smu + HS2B_OFF;           // [144 kp][8 m] split-2 pairs
    float*    exch = (float*)(smu + EXCH_OFF); // [8 m][JST]

    const int tid  = threadIdx.x;
    const int bg   = blockIdx.x >> 3;
    const int m0   = bg * MPB;
    const int n0   = (blockIdx.x & 7) * NPB;
    const int wid  = tid >> 5;
    const int lane = tid & 31;
    const int g    = lane >> 2;     // fragment group id
    const int tig  = lane & 3;      // thread-in-group
    const int mg   = tid >> 5;      // gate-phase batch row
    const int hc   = tid & 31;      // gate-phase h-col

    // this thread's two j rows and their gate rows / biases
    const int j0 = wid * 16 + g;
    const int j1 = j0 + 8;
    const int r0 = ((j0 & 3) << 8) + n0 + (j0 >> 2);
    const int r1 = ((j1 & 3) << 8) + n0 + (j1 >> 2);
    const float br0 = g_bias[r0];
    const float br1 = g_bias[r1];

    // staging index precompute (i = tid + it*256 -> m, kp)
    int st_m[5], st_kp[5];
    bool st_ok[5];
#pragma unroll
    for (int it = 0; it < 5; it++) {
        const int i = tid + it * 256;
        st_ok[it] = (i < NPAIR * MPB);
        st_m[it]  = i / NPAIR;
        st_kp[it] = i - st_m[it] * NPAIR;
    }

    // ---- one-time: A fragments (W 2-split) into registers ----
    uint32_t aw1[NKT][4], aw2[NKT][4];
#pragma unroll
    for (int kt = 0; kt < NKT; kt++) {
        const int kb = kt * 16 + 2 * tig;
#pragma unroll
        for (int sl = 0; sl < 4; sl++) {
            const int r = (sl & 1) ? r1 : r0;
            const int k = kb + ((sl >> 1) ? 8 : 0);
            float v0, v1;
            v0 = (k < HH)     ? W_hh[r * HH + k]     : g_Wcomb[r * DIN + (k - HH)];
            v1 = (k + 1 < HH) ? W_hh[r * HH + k + 1] : g_Wcomb[r * DIN + (k + 1 - HH)];
            split_pack(v0, v1, aw1[kt][sl], aw2[kt][sl]);
        }
    }

    float c_val = 0.0f;
    unsigned* cnt = &g_cnt[bg * 32];

    for (int t = 0; t < TT; t++) {
        const int p = t & 1;

        // ---- stage h(t)+x_t: batch all 5 loads (MLP=5), then split+store ----
        {
            float2 v[5];
#pragma unroll
            for (int it = 0; it < 5; it++) {
                if (st_ok[it]) {
                    const int m = st_m[it], kp = st_kp[it];
                    if (kp < 128)
                        v[it] = __ldcg((const float2*)&g_h[p][m0 + m][2 * kp]);
                    else
                        v[it] = *(const float2*)&x[((size_t)(m0 + m) * TT + t) * DIN
                                                   + 2 * (kp - 128)];
                }
            }
#pragma unroll
            for (int it = 0; it < 5; it++) {
                if (st_ok[it]) {
                    const int m = st_m[it], kp = st_kp[it];
                    uint32_t s1, s2;
                    split_pack(v[it].x, v[it].y, s1, s2);
                    hs2a[kp * 8 + m] = s1;
                    hs2b[kp * 8 + m] = s2;
                }
            }
        }
        __syncthreads();

        // ---- HMMA: 3 independent chains (W1h1 | W1h2 | W2h1), depth 18 ----
        float dA0 = br0, dA1 = br0, dA2 = br1, dA3 = br1;   // chain A carries bias
        float dB0 = 0.f, dB1 = 0.f, dB2 = 0.f, dB3 = 0.f;
        float dC0 = 0.f, dC1 = 0.f, dC2 = 0.f, dC3 = 0.f;
#pragma unroll
        for (int kt = 0; kt < NKT; kt++) {
            const uint32_t bA0 = hs2a[(kt * 8 + tig) * 8 + g];
            const uint32_t bA1 = hs2a[(kt * 8 + tig + 4) * 8 + g];
            const uint32_t bB0 = hs2b[(kt * 8 + tig) * 8 + g];
            const uint32_t bB1 = hs2b[(kt * 8 + tig + 4) * 8 + g];
            mma16816(dA0, dA1, dA2, dA3,
                     aw1[kt][0], aw1[kt][1], aw1[kt][2], aw1[kt][3], bA0, bA1);
            mma16816(dB0, dB1, dB2, dB3,
                     aw1[kt][0], aw1[kt][1], aw1[kt][2], aw1[kt][3], bB0, bB1);
            mma16816(dC0, dC1, dC2, dC3,
                     aw2[kt][0], aw2[kt][1], aw2[kt][2], aw2[kt][3], bA0, bA1);
        }
        const float d0 = (dA0 + dB0) + dC0;
        const float d1 = (dA1 + dB1) + dC1;
        const float d2 = (dA2 + dB2) + dC2;
        const float d3 = (dA3 + dB3) + dC3;

        // ---- epilogue: D frags -> exch[m][j] (JST=132 conflict-free) ----
        exch[(2 * tig)     * JST + j0] = d0;
        exch[(2 * tig + 1) * JST + j0] = d1;
        exch[(2 * tig)     * JST + j1] = d2;
        exch[(2 * tig + 1) * JST + j1] = d3;
        __syncthreads();

        // ---- gate phase: (mg, hc) reads quad (i,f,g,o), publish h(t+1) ----
        {
            const float4 q4 = *(const float4*)&exch[mg * JST + hc * 4];
            const float ig = fsig(q4.x);
            const float fg = fsig(q4.y);
            const float gg = ftanh(q4.z);
            const float og = fsig(q4.w);
            c_val = fmaf(fg, c_val, ig * gg);
            g_h[p ^ 1][m0 + mg][n0 + hc] = og * ftanh(c_val);
        }

        // ---- scoped group barrier (round-9 proven) ----
        __syncthreads();
        if (tid == 0) {
            red_add_release(cnt, 1u);
            const unsigned tgt = 8u * (unsigned)(t + 1);
            while (ld_acq(cnt) < tgt) { }
        }
        __syncthreads();
    }
    // h_last = h(2048) lives in g_h[0]
}

// ---------------- head: concat -> LayerNorm -> GELU(erf) MLP -> out ---------
__global__ void __launch_bounds__(256)
head_kernel(const float* __restrict__ ln_scale, const float* __restrict__ ln_bias,
            const float* __restrict__ W_h1, const float* __restrict__ b_h1,
            const float* __restrict__ W_h2, const float* __restrict__ b_h2,
            float* __restrict__ out)
{
    __shared__ __align__(16) float ns[512];
    __shared__ float red[32];
    __shared__ float mu_s, rv_s;

    const int b = blockIdx.x;
    const int tid = threadIdx.x;

    const float v0 = g_h[0][b][tid];
    const float v1 = g_ema_last[b * HH + tid];

    float s = v0 + v1, sq = v0 * v0 + v1 * v1;
#pragma unroll
    for (int o = 16; o; o >>= 1) {
        s  += __shfl_down_sync(0xffffffffu, s,  o);
        sq += __shfl_down_sync(0xffffffffu, sq, o);
    }
    if ((tid & 31) == 0) { red[tid >> 5] = s; red[8 + (tid >> 5)] = sq; }
    __syncthreads();
    if (tid == 0) {
        float ts = 0.f, tq = 0.f;
        for (int i = 0; i < 8; i++) { ts += red[i]; tq += red[8 + i]; }
        float mu = ts / 512.0f;
        mu_s = mu;
        rv_s = rsqrtf(tq / 512.0f - mu * mu + 1e-5f);
    }
    __syncthreads();
    const float mu = mu_s, ri = rv_s;
    ns[tid]       = fmaf((v0 - mu) * ri, ln_scale[tid],       ln_bias[tid]);
    ns[tid + 256] = fmaf((v1 - mu) * ri, ln_scale[tid + 256], ln_bias[tid + 256]);
    __syncthreads();

    float acc = b_h1[tid];
    const float4* wr = (const float4*)(W_h1 + (size_t)tid * 512);
#pragma unroll 8
    for (int q = 0; q < 128; q++) {
        float4 w = wr[q];
        float4 n = *(const float4*)&ns[q * 4];
        acc = fmaf(w.x, n.x, acc); acc = fmaf(w.y, n.y, acc);
        acc = fmaf(w.z, n.z, acc); acc = fmaf(w.w, n.w, acc);
    }
    float g1 = 0.5f * acc * (1.0f + erff(acc * 0.70710678118654752f));
    float p = g1 * W_h2[tid];
#pragma unroll
    for (int o = 16; o; o >>= 1) p += __shfl_down_sync(0xffffffffu, p, o);
    if ((tid & 31) == 0) red[16 + (tid >> 5)] = p;
    __syncthreads();
    if (tid == 0) {
        float tsum = b_h2[0];
        for (int i = 0; i < 8; i++) tsum += red[16 + i];
        out[b] = tsum;
    }
}

// ---------------- launch ----------------------------------------------------
extern "C" void kernel_launch(void* const* d_in, const int* in_sizes, int n_in,
                              void* d_out, int out_size)
{
    (void)in_sizes; (void)n_in; (void)out_size;
    const float* x        = (const float*)d_in[0];
    const float* W_in     = (const float*)d_in[1];
    const float* b_in     = (const float*)d_in[2];
    const float* W_ih     = (const float*)d_in[3];
    const float* W_hh     = (const float*)d_in[4];
    const float* b_ih     = (const float*)d_in[5];
    const float* b_hh     = (const float*)d_in[6];
    const float* W_proj   = (const float*)d_in[7];
    const float* b_proj   = (const float*)d_in[8];
    const float* W_gate   = (const float*)d_in[9];
    const float* b_gate   = (const float*)d_in[10];
    const float* ln_scale = (const float*)d_in[11];
    const float* ln_bias  = (const float*)d_in[12];
    const float* W_h1     = (const float*)d_in[13];
    const float* b_h1     = (const float*)d_in[14];
    const float* W_h2     = (const float*)d_in[15];
    const float* b_h2     = (const float*)d_in[16];
    float* out = (float*)d_out;

    cudaFuncSetAttribute(recur_kernel,
                         cudaFuncAttributeMaxDynamicSharedMemorySize, SMEM_BYTES);

    prep_kernel<<<132, 256>>>(W_in, b_in, W_ih, b_ih, b_hh);
    recur_kernel<<<NBLK, 256, SMEM_BYTES>>>(x, W_hh);
    ema_scan_kernel<<<BB * 32, 256>>>(x, W_proj, b_proj, W_gate, b_gate);
    ema_combine_kernel<<<BB, 256>>>();
    head_kernel<<<BB, 256>>>(ln_scale, ln_bias, W_h1, b_h1, W_h2, b_h2, out);
}